// round 16
// baseline (speedup 1.0000x reference)
#include <cuda_runtime.h>

typedef unsigned long long u64;
typedef unsigned int u32;

#define NB 2
#define NH 12
#define SQ 1024
#define DK 64
#define DM 768

// ---------------- scratch ----------------
__device__ float g_q[NB*NH*SQ*DK];                 // pre-scaled by 1/64
__device__ float g_k[NB*NH*SQ*DK];
__device__ float g_v[NB*NH*SQ*DK];
__device__ float g_scores[(size_t)NB*NH*SQ*SQ];    // scores, then probs (in place)
__device__ float g_attn[NB*SQ*DM];                 // w_rel
__device__ float g_attn2[NB*SQ*DM];                // wv partial (k 0..511)
__device__ float g_attn3[NB*SQ*DM];                // wv partial (k 512..1023)

// ---------------- tf32 mma helpers ----------------
__device__ __forceinline__ u32 to_tf32(float f){
    u32 u; asm("cvt.rna.tf32.f32 %0, %1;" : "=r"(u) : "f"(f)); return u;
}
__device__ __forceinline__ uint4 cvt4(float4 v){
    uint4 u; u.x = to_tf32(v.x); u.y = to_tf32(v.y); u.z = to_tf32(v.z); u.w = to_tf32(v.w);
    return u;
}
__device__ __forceinline__ void mma_tf32(float* c, const u32* a, const u32* b){
    asm volatile(
        "mma.sync.aligned.m16n8k8.row.col.f32.tf32.tf32.f32 "
        "{%0,%1,%2,%3}, {%4,%5,%6,%7}, {%8,%9}, {%0,%1,%2,%3};"
        : "+f"(c[0]), "+f"(c[1]), "+f"(c[2]), "+f"(c[3])
        : "r"(a[0]), "r"(a[1]), "r"(a[2]), "r"(a[3]), "r"(b[0]), "r"(b[1]));
}

// =====================================================================
// K1: QKV projections via tf32 mma. grid (16, 12, 3). 256 thr, static smem.
// =====================================================================
__global__ __launch_bounds__(256) void k_proj(
    const float* __restrict__ Xq, const float* __restrict__ Xk, const float* __restrict__ Xv,
    const float* __restrict__ Wq, const float* __restrict__ Wk, const float* __restrict__ Wv,
    const float* __restrict__ bq, const float* __restrict__ bk, const float* __restrict__ bv)
{
    const int z = blockIdx.z;
    const float* X    = (z == 0) ? Xq : (z == 1) ? Xk : Xv;
    const float* W    = (z == 0) ? Wq : (z == 1) ? Wk : Wv;
    const float* bias = (z == 0) ? bq : (z == 1) ? bk : bv;
    float* out        = (z == 0) ? g_q : (z == 1) ? g_k : g_v;
    const float scale = (z == 0) ? (1.0f / 64.0f) : 1.0f;

    __shared__ __align__(16) u32 As[128][36];
    __shared__ __align__(16) u32 Bs[32][72];

    const int tid = threadIdx.x;
    const int lane = tid & 31;
    const int warp = tid >> 5;
    const int wm = warp >> 1;
    const int wn = warp & 1;
    const int rq = lane >> 2;
    const int cq = lane & 3;
    const int m0 = blockIdx.x * 128;
    const int h  = blockIdx.y;
    const int n0 = h * 64;

    float acc[2][4][4];
    #pragma unroll
    for (int i = 0; i < 2; i++)
        #pragma unroll
        for (int j = 0; j < 4; j++)
            #pragma unroll
            for (int t = 0; t < 4; t++) acc[i][j][t] = 0.f;

    float4 pfa[4], pfb[2];
    #pragma unroll
    for (int it = 0; it < 4; it++) {
        int f = tid + it * 256;
        pfa[it] = *(const float4*)(X + (size_t)(m0 + (f >> 3)) * DM + (f & 7) * 4);
    }
    #pragma unroll
    for (int it = 0; it < 2; it++) {
        int f = tid + it * 256;
        pfb[it] = *(const float4*)(W + (size_t)(f >> 4) * DM + n0 + (f & 15) * 4);
    }

    for (int k0 = 0; k0 < DM; k0 += 32) {
        __syncthreads();
        #pragma unroll
        for (int it = 0; it < 4; it++) {
            int f = tid + it * 256;
            *(uint4*)&As[f >> 3][(f & 7) * 4] = cvt4(pfa[it]);
        }
        #pragma unroll
        for (int it = 0; it < 2; it++) {
            int f = tid + it * 256;
            *(uint4*)&Bs[f >> 4][(f & 15) * 4] = cvt4(pfb[it]);
        }
        __syncthreads();

        if (k0 + 32 < DM) {
            #pragma unroll
            for (int it = 0; it < 4; it++) {
                int f = tid + it * 256;
                pfa[it] = *(const float4*)(X + (size_t)(m0 + (f >> 3)) * DM + k0 + 32 + (f & 7) * 4);
            }
            #pragma unroll
            for (int it = 0; it < 2; it++) {
                int f = tid + it * 256;
                pfb[it] = *(const float4*)(W + (size_t)(k0 + 32 + (f >> 4)) * DM + n0 + (f & 15) * 4);
            }
        }

        #pragma unroll
        for (int ks = 0; ks < 4; ks++) {
            int kk = ks * 8;
            u32 a[2][4], bf[4][2];
            #pragma unroll
            for (int mi = 0; mi < 2; mi++) {
                int r = wm * 32 + mi * 16 + rq;
                a[mi][0] = As[r][kk + cq];
                a[mi][1] = As[r + 8][kk + cq];
                a[mi][2] = As[r][kk + cq + 4];
                a[mi][3] = As[r + 8][kk + cq + 4];
            }
            #pragma unroll
            for (int ni = 0; ni < 4; ni++) {
                int n = wn * 32 + ni * 8 + rq;
                bf[ni][0] = Bs[kk + cq][n];
                bf[ni][1] = Bs[kk + cq + 4][n];
            }
            #pragma unroll
            for (int mi = 0; mi < 2; mi++)
                #pragma unroll
                for (int ni = 0; ni < 4; ni++)
                    mma_tf32(acc[mi][ni], a[mi], bf[ni]);
        }
    }

    #pragma unroll
    for (int mi = 0; mi < 2; mi++) {
        #pragma unroll
        for (int ni = 0; ni < 4; ni++) {
            int ncol = wn * 32 + ni * 8 + cq * 2;
            float bx = bias[n0 + ncol];
            float by = bias[n0 + ncol + 1];
            int m = m0 + wm * 32 + mi * 16 + rq;
            {
                int b = m >> 10, s = m & (SQ - 1);
                float* dst = out + ((size_t)((b * NH + h) * SQ + s)) * DK + ncol;
                *(float2*)dst = make_float2((acc[mi][ni][0] + bx) * scale,
                                            (acc[mi][ni][1] + by) * scale);
            }
            {
                int m2 = m + 8;
                int b = m2 >> 10, s = m2 & (SQ - 1);
                float* dst = out + ((size_t)((b * NH + h) * SQ + s)) * DK + ncol;
                *(float2*)dst = make_float2((acc[mi][ni][2] + bx) * scale,
                                            (acc[mi][ni][3] + by) * scale);
            }
        }
    }
}

// =====================================================================
// device fn: scores tile = q @ k^T for head bh, tile (bx, by). 256 thr.
// smem: 2 * 128*68 u32 = 69632 B
// =====================================================================
__device__ __forceinline__ void dev_qk(int bh, int bx, int by, char* smraw)
{
    u32 (*Qs)[68] = (u32(*)[68])smraw;
    u32 (*Ks)[68] = (u32(*)[68])(smraw + 128 * 68 * 4);

    const float* Aq = g_q + (size_t)bh * SQ * DK;
    const float* Bk = g_k + (size_t)bh * SQ * DK;
    float* C = g_scores + (size_t)bh * SQ * SQ;

    const int m0 = bx * 128;
    const int n0 = by * 128;
    const int tid = threadIdx.x;
    const int lane = tid & 31;
    const int warp = tid >> 5;
    const int wm = warp >> 2;
    const int wn = warp & 3;
    const int rq = lane >> 2;
    const int cq = lane & 3;

    #pragma unroll
    for (int it = 0; it < 8; it++) {
        int f = tid + it * 256;
        int r  = f >> 4;
        int d4 = (f & 15) * 4;
        float4 va = *(const float4*)(Aq + (size_t)(m0 + r) * DK + d4);
        float4 vb = *(const float4*)(Bk + (size_t)(n0 + r) * DK + d4);
        *(uint4*)&Qs[r][d4] = cvt4(va);
        *(uint4*)&Ks[r][d4] = cvt4(vb);
    }
    __syncthreads();

    float acc[4][4][4];
    #pragma unroll
    for (int i = 0; i < 4; i++)
        #pragma unroll
        for (int j = 0; j < 4; j++)
            #pragma unroll
            for (int t = 0; t < 4; t++) acc[i][j][t] = 0.f;

    #pragma unroll
    for (int ks = 0; ks < 8; ks++) {
        int d0 = ks * 8;
        u32 a[4][4], bf[4][2];
        #pragma unroll
        for (int mi = 0; mi < 4; mi++) {
            int r = wm * 64 + mi * 16 + rq;
            a[mi][0] = Qs[r][d0 + cq];
            a[mi][1] = Qs[r + 8][d0 + cq];
            a[mi][2] = Qs[r][d0 + cq + 4];
            a[mi][3] = Qs[r + 8][d0 + cq + 4];
        }
        #pragma unroll
        for (int ni = 0; ni < 4; ni++) {
            int n = wn * 32 + ni * 8 + rq;
            bf[ni][0] = Ks[n][d0 + cq];
            bf[ni][1] = Ks[n][d0 + cq + 4];
        }
        #pragma unroll
        for (int mi = 0; mi < 4; mi++)
            #pragma unroll
            for (int ni = 0; ni < 4; ni++)
                mma_tf32(acc[mi][ni], a[mi], bf[ni]);
    }

    #pragma unroll
    for (int mi = 0; mi < 4; mi++) {
        #pragma unroll
        for (int ni = 0; ni < 4; ni++) {
            int r0 = m0 + wm * 64 + mi * 16 + rq;
            int c0 = n0 + wn * 32 + ni * 8 + cq * 2;
            *(float2*)(C + (size_t)r0 * SQ + c0)       = make_float2(acc[mi][ni][0], acc[mi][ni][1]);
            *(float2*)(C + (size_t)(r0 + 8) * SQ + c0) = make_float2(acc[mi][ni][2], acc[mi][ni][3]);
        }
    }
}

// =====================================================================
// device fn: qrel + softmax for (b, q). 256 threads (8 warps; warp owns
// 16 chunk-cols = 2 mma n-groups). smem 88064 B.
// =====================================================================
__device__ __forceinline__ void dev_qrel(const float* __restrict__ relk,
                                         int b, int q, char* smraw)
{
    float* ss = (float*)smraw;                                   // 12*1024 f
    u32 (*rks)[68] = (u32(*)[68])(smraw + NH * SQ * 4);          // 128x68
    u32 (*qs)[64]  = (u32(*)[64])(smraw + NH * SQ * 4 + 128 * 68 * 4); // 16x64

    const int tid = threadIdx.x;
    const int lane = tid & 31;
    const int warp = tid >> 5;       // 0..7
    const int rq = lane >> 2;
    const int cq = lane & 3;
    const int n0c = warp * 16;

    if (tid < 192) {
        int hh = tid >> 4;
        int d4 = (tid & 15) * 4;
        float4 v = *(const float4*)(g_q + ((size_t)((b * NH + hh) * SQ + q)) * DK + d4);
        *(uint4*)&qs[hh][d4] = cvt4(v);
    } else {
        int r = 12 + ((tid - 192) >> 4);
        int d4 = ((tid - 192) & 15) * 4;
        *(uint4*)&qs[r][d4] = make_uint4(0u, 0u, 0u, 0u);
    }
    #pragma unroll
    for (int it = 0; it < 12; it++) {
        int f = tid + it * 256;
        int hh = f >> 8;
        int k4 = (f & 255) * 4;
        *(float4*)&ss[hh * SQ + k4] =
            *(const float4*)(g_scores + ((size_t)((b * NH + hh) * SQ + q)) * SQ + k4);
    }

    const float* relbase = relk + ((size_t)(b * SQ + q)) * SQ * DK;

    float4 pf[8];
    #pragma unroll
    for (int it = 0; it < 8; it++) {
        int f = tid + it * 256;
        pf[it] = *(const float4*)(relbase + (size_t)(f >> 4) * DK + (f & 15) * 4);
    }

    for (int kt = 0; kt < SQ; kt += 128) {
        __syncthreads();
        #pragma unroll
        for (int it = 0; it < 8; it++) {
            int f = tid + it * 256;
            *(uint4*)&rks[f >> 4][(f & 15) * 4] = cvt4(pf[it]);
        }
        __syncthreads();

        if (kt + 128 < SQ) {
            #pragma unroll
            for (int it = 0; it < 8; it++) {
                int f = tid + it * 256;
                pf[it] = *(const float4*)(relbase + (size_t)(kt + 128 + (f >> 4)) * DK + (f & 15) * 4);
            }
        }

        float acc[2][4];
        #pragma unroll
        for (int g = 0; g < 2; g++)
            #pragma unroll
            for (int t = 0; t < 4; t++) acc[g][t] = 0.f;

        #pragma unroll
        for (int ks = 0; ks < 8; ks++) {
            int d0 = ks * 8;
            u32 a[4];
            a[0] = qs[rq][d0 + cq];
            a[1] = qs[rq + 8][d0 + cq];
            a[2] = qs[rq][d0 + cq + 4];
            a[3] = qs[rq + 8][d0 + cq + 4];
            #pragma unroll
            for (int g = 0; g < 2; g++) {
                u32 bf[2];
                bf[0] = rks[n0c + g * 8 + rq][d0 + cq];
                bf[1] = rks[n0c + g * 8 + rq][d0 + cq + 4];
                mma_tf32(acc[g], a, bf);
            }
        }

        #pragma unroll
        for (int g = 0; g < 2; g++) {
            int col = kt + n0c + g * 8 + cq * 2;
            ss[rq * SQ + col]     += acc[g][0];
            ss[rq * SQ + col + 1] += acc[g][1];
            if (rq < 4) {
                ss[(rq + 8) * SQ + col]     += acc[g][2];
                ss[(rq + 8) * SQ + col + 1] += acc[g][3];
            }
        }
    }
    __syncthreads();

    // softmax: 8 warps cover 12 rows
    for (int r = warp; r < NH; r += 8) {
        float* p = ss + r * SQ;
        float4 v[8];
        float mx = -3.4e38f;
        #pragma unroll
        for (int j = 0; j < 8; j++) {
            v[j] = *(float4*)(p + lane * 4 + j * 128);
            mx = fmaxf(mx, fmaxf(fmaxf(v[j].x, v[j].y), fmaxf(v[j].z, v[j].w)));
        }
        #pragma unroll
        for (int o = 16; o > 0; o >>= 1) mx = fmaxf(mx, __shfl_xor_sync(0xffffffffu, mx, o));

        float s = 0.f;
        #pragma unroll
        for (int j = 0; j < 8; j++) {
            v[j].x = __expf(v[j].x - mx);
            v[j].y = __expf(v[j].y - mx);
            v[j].z = __expf(v[j].z - mx);
            v[j].w = __expf(v[j].w - mx);
            s += v[j].x + v[j].y + v[j].z + v[j].w;
        }
        #pragma unroll
        for (int o = 16; o > 0; o >>= 1) s += __shfl_xor_sync(0xffffffffu, s, o);
        const float inv = 1.0f / s;

        float* dst = g_scores + ((size_t)((b * NH + r) * SQ + q)) * SQ;
        #pragma unroll
        for (int j = 0; j < 8; j++) {
            v[j].x *= inv; v[j].y *= inv; v[j].z *= inv; v[j].w *= inv;
            *(float4*)(dst + lane * 4 + j * 128) = v[j];
        }
    }
}

// =====================================================================
// device fn: w_rel for (b, q). 256 threads. smem 45312 B.
// =====================================================================
__device__ __forceinline__ void dev_wrel(const float* __restrict__ relv,
                                         int b, int q, char* smraw)
{
    u32 (*rvs)[72] = (u32(*)[72])smraw;                     // 128x72
    u32 (*ps)[132] = (u32(*)[132])(smraw + 128 * 72 * 4);   // 16x132

    const int tid = threadIdx.x;
    const int lane = tid & 31;
    const int warp = tid >> 5;
    const int rq = lane >> 2;
    const int cq = lane & 3;
    const int n0c = warp * 8;

    {
        int r = 12 + (tid >> 6);
        int c = (tid & 63) * 2;
        ps[r][c] = 0u; ps[r][c + 1] = 0u;
    }

    const float* relbase = relv + ((size_t)(b * SQ + q)) * SQ * DK;
    const float* psrc = g_scores + ((size_t)(b * NH) * SQ + q) * SQ;

    float acc[4] = {0.f, 0.f, 0.f, 0.f};

    float4 pfr[8], pfp[2];
    #pragma unroll
    for (int it = 0; it < 8; it++) {
        int f = tid + it * 256;
        pfr[it] = *(const float4*)(relbase + (size_t)(f >> 4) * DK + (f & 15) * 4);
    }
    #pragma unroll
    for (int it = 0; it < 2; it++) {
        int f = tid + it * 256;
        if (f < 384)
            pfp[it] = *(const float4*)(psrc + (size_t)(f >> 5) * SQ * SQ + (f & 31) * 4);
    }

    for (int kt = 0; kt < SQ; kt += 128) {
        __syncthreads();
        #pragma unroll
        for (int it = 0; it < 8; it++) {
            int f = tid + it * 256;
            *(uint4*)&rvs[f >> 4][(f & 15) * 4] = cvt4(pfr[it]);
        }
        #pragma unroll
        for (int it = 0; it < 2; it++) {
            int f = tid + it * 256;
            if (f < 384)
                *(uint4*)&ps[f >> 5][(f & 31) * 4] = cvt4(pfp[it]);
        }
        __syncthreads();

        if (kt + 128 < SQ) {
            #pragma unroll
            for (int it = 0; it < 8; it++) {
                int f = tid + it * 256;
                pfr[it] = *(const float4*)(relbase + (size_t)(kt + 128 + (f >> 4)) * DK + (f & 15) * 4);
            }
            #pragma unroll
            for (int it = 0; it < 2; it++) {
                int f = tid + it * 256;
                if (f < 384)
                    pfp[it] = *(const float4*)(psrc + (size_t)(f >> 5) * SQ * SQ + kt + 128 + (f & 31) * 4);
            }
        }

        #pragma unroll
        for (int ks = 0; ks < 16; ks++) {
            int kk = ks * 8;
            u32 a[4], bf[2];
            a[0] = ps[rq][kk + cq];
            a[1] = ps[rq + 8][kk + cq];
            a[2] = ps[rq][kk + cq + 4];
            a[3] = ps[rq + 8][kk + cq + 4];
            bf[0] = rvs[kk + cq][n0c + rq];
            bf[1] = rvs[kk + cq + 4][n0c + rq];
            mma_tf32(acc, a, bf);
        }
    }

    const size_t base = (size_t)(b * SQ + q) * DM;
    const int col = n0c + cq * 2;
    *(float2*)(g_attn + base + rq * DK + col) = make_float2(acc[0], acc[1]);
    if (rq < 4)
        *(float2*)(g_attn + base + (rq + 8) * DK + col) = make_float2(acc[2], acc[3]);
}

// =====================================================================
// device fn: wv tile for batch b, idx2 in [0, 192). 256 threads.
// smem 27648 B (128x36 + 32x72 u32).
// =====================================================================
__device__ __forceinline__ void dev_wv(int b, int idx2, char* smraw)
{
    u32 (*As)[36] = (u32(*)[36])smraw;
    u32 (*Bs)[72] = (u32(*)[72])(smraw + 128 * 36 * 4);

    const int m0 = (idx2 & 7) * 128;
    const int h = (idx2 >> 3) % NH;
    const int kz = idx2 / 96;
    const int bh = b * NH + h;
    const int koff = kz * 512;
    const float* A  = g_scores + (size_t)bh * SQ * SQ + koff;
    const float* Bv = g_v + ((size_t)bh * SQ + koff) * DK;
    float* outp = kz ? g_attn3 : g_attn2;

    const int tid = threadIdx.x;
    const int lane = tid & 31;
    const int warp = tid >> 5;
    const int wm = warp >> 1;
    const int wn = warp & 1;
    const int rq = lane >> 2;
    const int cq = lane & 3;

    float acc[2][4][4];
    #pragma unroll
    for (int i = 0; i < 2; i++)
        #pragma unroll
        for (int j = 0; j < 4; j++)
            #pragma unroll
            for (int t = 0; t < 4; t++) acc[i][j][t] = 0.f;

    float4 pfa[4], pfb[2];
    #pragma unroll
    for (int it = 0; it < 4; it++) {
        int f = tid + it * 256;
        pfa[it] = *(const float4*)(A + (size_t)(m0 + (f >> 3)) * SQ + (f & 7) * 4);
    }
    #pragma unroll
    for (int it = 0; it < 2; it++) {
        int f = tid + it * 256;
        pfb[it] = *(const float4*)(Bv + (size_t)(f >> 4) * DK + (f & 15) * 4);
    }

    for (int k0 = 0; k0 < 512; k0 += 32) {
        __syncthreads();
        #pragma unroll
        for (int it = 0; it < 4; it++) {
            int f = tid + it * 256;
            *(uint4*)&As[f >> 3][(f & 7) * 4] = cvt4(pfa[it]);
        }
        #pragma unroll
        for (int it = 0; it < 2; it++) {
            int f = tid + it * 256;
            *(uint4*)&Bs[f >> 4][(f & 15) * 4] = cvt4(pfb[it]);
        }
        __syncthreads();

        if (k0 + 32 < 512) {
            #pragma unroll
            for (int it = 0; it < 4; it++) {
                int f = tid + it * 256;
                pfa[it] = *(const float4*)(A + (size_t)(m0 + (f >> 3)) * SQ + k0 + 32 + (f & 7) * 4);
            }
            #pragma unroll
            for (int it = 0; it < 2; it++) {
                int f = tid + it * 256;
                pfb[it] = *(const float4*)(Bv + (size_t)(k0 + 32 + (f >> 4)) * DK + (f & 15) * 4);
            }
        }

        #pragma unroll
        for (int ks = 0; ks < 4; ks++) {
            int kk = ks * 8;
            u32 a[2][4], bf[4][2];
            #pragma unroll
            for (int mi = 0; mi < 2; mi++) {
                int r = wm * 32 + mi * 16 + rq;
                a[mi][0] = As[r][kk + cq];
                a[mi][1] = As[r + 8][kk + cq];
                a[mi][2] = As[r][kk + cq + 4];
                a[mi][3] = As[r + 8][kk + cq + 4];
            }
            #pragma unroll
            for (int ni = 0; ni < 4; ni++) {
                int n = wn * 32 + ni * 8 + rq;
                bf[ni][0] = Bs[kk + cq][n];
                bf[ni][1] = Bs[kk + cq + 4][n];
            }
            #pragma unroll
            for (int mi = 0; mi < 2; mi++)
                #pragma unroll
                for (int ni = 0; ni < 4; ni++)
                    mma_tf32(acc[mi][ni], a[mi], bf[ni]);
        }
    }

    #pragma unroll
    for (int mi = 0; mi < 2; mi++) {
        #pragma unroll
        for (int ni = 0; ni < 4; ni++) {
            int r0 = m0 + wm * 32 + mi * 16 + rq;
            int c0 = wn * 32 + ni * 8 + cq * 2;
            float* dst0 = outp + (size_t)(b * SQ + r0) * DM + h * DK + c0;
            float* dst1 = outp + (size_t)(b * SQ + r0 + 8) * DM + h * DK + c0;
            *(float2*)dst0 = make_float2(acc[mi][ni][0], acc[mi][ni][1]);
            *(float2*)dst1 = make_float2(acc[mi][ni][2], acc[mi][ni][3]);
        }
    }
}

// =====================================================================
// device fn: output projection tile. rows [mbase + bx*64, +64), cols
// [by*64, +64). 256 threads. smem 18432 B.
// =====================================================================
__device__ __forceinline__ void dev_out(
    const float* __restrict__ Wo, const float* __restrict__ bo,
    float* __restrict__ out, int bx, int by, int mbase, char* smraw)
{
    u32 (*As)[36] = (u32(*)[36])smraw;
    u32 (*Bs)[72] = (u32(*)[72])(smraw + 64 * 36 * 4);

    const int tid = threadIdx.x;
    const int lane = tid & 31;
    const int warp = tid >> 5;
    const int wm = warp >> 1;
    const int wn = warp & 1;
    const int rq = lane >> 2;
    const int cq = lane & 3;
    const int m0 = mbase + bx * 64;
    const int n0 = by * 64;

    float acc[4][4];
    #pragma unroll
    for (int j = 0; j < 4; j++)
        #pragma unroll
        for (int t = 0; t < 4; t++) acc[j][t] = 0.f;

    float4 pfa[2], pfb[2];
    #pragma unroll
    for (int it = 0; it < 2; it++) {
        int f = tid + it * 256;
        size_t idx = (size_t)(m0 + (f >> 3)) * DM + (f & 7) * 4;
        float4 a1 = *(const float4*)(g_attn + idx);
        float4 a2 = *(const float4*)(g_attn2 + idx);
        float4 a3 = *(const float4*)(g_attn3 + idx);
        pfa[it] = make_float4(a1.x + a2.x + a3.x, a1.y + a2.y + a3.y,
                              a1.z + a2.z + a3.z, a1.w + a2.w + a3.w);
        pfb[it] = *(const float4*)(Wo + (size_t)(f >> 4) * DM + n0 + (f & 15) * 4);
    }

    for (int k0 = 0; k0 < DM; k0 += 32) {
        __syncthreads();
        #pragma unroll
        for (int it = 0; it < 2; it++) {
            int f = tid + it * 256;
            *(uint4*)&As[f >> 3][(f & 7) * 4] = cvt4(pfa[it]);
            *(uint4*)&Bs[f >> 4][(f & 15) * 4] = cvt4(pfb[it]);
        }
        __syncthreads();

        if (k0 + 32 < DM) {
            #pragma unroll
            for (int it = 0; it < 2; it++) {
                int f = tid + it * 256;
                size_t idx = (size_t)(m0 + (f >> 3)) * DM + k0 + 32 + (f & 7) * 4;
                float4 a1 = *(const float4*)(g_attn + idx);
                float4 a2 = *(const float4*)(g_attn2 + idx);
                float4 a3 = *(const float4*)(g_attn3 + idx);
                pfa[it] = make_float4(a1.x + a2.x + a3.x, a1.y + a2.y + a3.y,
                                      a1.z + a2.z + a3.z, a1.w + a2.w + a3.w);
                pfb[it] = *(const float4*)(Wo + (size_t)(k0 + 32 + (f >> 4)) * DM + n0 + (f & 15) * 4);
            }
        }

        #pragma unroll
        for (int ks = 0; ks < 4; ks++) {
            int kk = ks * 8;
            u32 a[4], bf[4][2];
            int r = wm * 16 + rq;
            a[0] = As[r][kk + cq];
            a[1] = As[r + 8][kk + cq];
            a[2] = As[r][kk + cq + 4];
            a[3] = As[r + 8][kk + cq + 4];
            #pragma unroll
            for (int ni = 0; ni < 4; ni++) {
                int n = wn * 32 + ni * 8 + rq;
                bf[ni][0] = Bs[kk + cq][n];
                bf[ni][1] = Bs[kk + cq + 4][n];
            }
            #pragma unroll
            for (int ni = 0; ni < 4; ni++)
                mma_tf32(acc[ni], a, bf[ni]);
        }
    }

    #pragma unroll
    for (int ni = 0; ni < 4; ni++) {
        int ncol = wn * 32 + ni * 8 + cq * 2;
        float bx2 = bo[n0 + ncol];
        float by2 = bo[n0 + ncol + 1];
        int m = m0 + wm * 16 + rq;
        *(float2*)(out + (size_t)m * DM + n0 + ncol) =
            make_float2(acc[ni][0] + bx2, acc[ni][1] + by2);
        *(float2*)(out + (size_t)(m + 8) * DM + n0 + ncol) =
            make_float2(acc[ni][2] + bx2, acc[ni][3] + by2);
    }
}

// =====================================================================
// global kernels (all 256 threads, dynamic smem)
// =====================================================================
__global__ __launch_bounds__(256) void k_qk0()
{
    extern __shared__ char smraw[];
    dev_qk(blockIdx.z, blockIdx.x, blockIdx.y, smraw);   // b = 0
}

// qrel(b0) [0,1024) + qk(b1) [1024, 1792)
__global__ __launch_bounds__(256) void k_mix1(const float* __restrict__ relk)
{
    extern __shared__ char smraw[];
    int i = blockIdx.x;
    if (i < 1024) {
        dev_qrel(relk, 0, i, smraw);
    } else {
        int j = i - 1024;
        dev_qk(NH + (j >> 6), j & 7, (j >> 3) & 7, smraw);
    }
}

// qrel(b1) [0,1024) + wrel(b0) [1024,2048) + wv(b0) [2048,2240)
__global__ __launch_bounds__(256) void k_mix2(const float* __restrict__ relk,
                                              const float* __restrict__ relv)
{
    extern __shared__ char smraw[];
    int i = blockIdx.x;
    if (i < 1024) {
        dev_qrel(relk, 1, i, smraw);
    } else if (i < 2048) {
        dev_wrel(relv, 0, i - 1024, smraw);
    } else {
        dev_wv(0, i - 2048, smraw);
    }
}

// wrel(b1) [0,1024) + wv(b1) [1024,1216) + out(b0) [1216,1408)
__global__ __launch_bounds__(256) void k_mix3(const float* __restrict__ relv,
                                              const float* __restrict__ Wo,
                                              const float* __restrict__ bo,
                                              float* __restrict__ out)
{
    extern __shared__ char smraw[];
    int i = blockIdx.x;
    if (i < 1024) {
        dev_wrel(relv, 1, i, smraw);
    } else if (i < 1216) {
        dev_wv(1, i - 1024, smraw);
    } else {
        int j = i - 1216;
        dev_out(Wo, bo, out, j & 15, j >> 4, 0, smraw);
    }
}

// out(b1): grid (16, 12)
__global__ __launch_bounds__(256) void k_out1(const float* __restrict__ Wo,
                                              const float* __restrict__ bo,
                                              float* __restrict__ out)
{
    extern __shared__ char smraw[];
    dev_out(Wo, bo, out, blockIdx.x, blockIdx.y, SQ, smraw);
}

// =====================================================================
extern "C" void kernel_launch(void* const* d_in, const int* in_sizes, int n_in,
                              void* d_out, int out_size)
{
    const float* queries = (const float*)d_in[0];
    const float* keys    = (const float*)d_in[1];
    const float* values  = (const float*)d_in[2];
    const float* relk    = (const float*)d_in[3];
    const float* relv    = (const float*)d_in[4];
    const float* Wq = (const float*)d_in[5];
    const float* bq = (const float*)d_in[6];
    const float* Wk = (const float*)d_in[7];
    const float* bk = (const float*)d_in[8];
    const float* Wv = (const float*)d_in[9];
    const float* bv = (const float*)d_in[10];
    const float* Wo = (const float*)d_in[11];
    const float* bo = (const float*)d_in[12];
    float* out = (float*)d_out;

    const int qk_smem   = 2 * 128 * 68 * (int)sizeof(u32);               // 69632
    const int qrel_smem = NH * SQ * (int)sizeof(float)
                        + 128 * 68 * (int)sizeof(u32)
                        + 16 * 64 * (int)sizeof(u32);                    // 88064
    const int pv_smem   = (128 * 72 + 16 * 132) * (int)sizeof(u32);      // 45312
    const int out_smem  = (64 * 36 + 32 * 72) * (int)sizeof(u32);        // 18432

    static bool attr_set = false;
    if (!attr_set) {
        cudaFuncSetAttribute(k_qk0, cudaFuncAttributeMaxDynamicSharedMemorySize, qk_smem);
        cudaFuncSetAttribute(k_mix1, cudaFuncAttributeMaxDynamicSharedMemorySize, qrel_smem);
        cudaFuncSetAttribute(k_mix2, cudaFuncAttributeMaxDynamicSharedMemorySize, qrel_smem);
        cudaFuncSetAttribute(k_mix3, cudaFuncAttributeMaxDynamicSharedMemorySize, pv_smem);
        cudaFuncSetAttribute(k_out1, cudaFuncAttributeMaxDynamicSharedMemorySize, out_smem);
        attr_set = true;
    }

    k_proj<<<dim3(16, 12, 3), 256>>>(queries, keys, values, Wq, Wk, Wv, bq, bk, bv);
    k_qk0<<<dim3(8, 8, NH), 256, qk_smem>>>();
    k_mix1<<<dim3(1024 + 768), 256, qrel_smem>>>(relk);
    k_mix2<<<dim3(1024 + 1024 + 192), 256, qrel_smem>>>(relk, relv);
    k_mix3<<<dim3(1024 + 192 + 192), 256, pv_smem>>>(relv, Wo, bo, out);
    k_out1<<<dim3(16, 12), 256, out_smem>>>(Wo, bo, out);
}

// round 17
// speedup vs baseline: 1.2618x; 1.2618x over previous
#include <cuda_runtime.h>

typedef unsigned long long u64;
typedef unsigned int u32;

#define NB 2
#define NH 12
#define SQ 1024
#define DK 64
#define DM 768

// ---------------- scratch ----------------
__device__ float g_q[NB*NH*SQ*DK];                 // pre-scaled by 1/64
__device__ float g_k[NB*NH*SQ*DK];
__device__ float g_v[NB*NH*SQ*DK];
__device__ float g_scores[(size_t)NB*NH*SQ*SQ];    // scores, then probs (in place)
__device__ float g_attn[NB*SQ*DM];                 // w_rel
__device__ float g_attn2[NB*SQ*DM];                // wv partial (k 0..511)
__device__ float g_attn3[NB*SQ*DM];                // wv partial (k 512..1023)

// ---------------- tf32 mma helpers ----------------
__device__ __forceinline__ u32 to_tf32(float f){
    u32 u; asm("cvt.rna.tf32.f32 %0, %1;" : "=r"(u) : "f"(f)); return u;
}
__device__ __forceinline__ uint4 cvt4(float4 v){
    uint4 u; u.x = to_tf32(v.x); u.y = to_tf32(v.y); u.z = to_tf32(v.z); u.w = to_tf32(v.w);
    return u;
}
__device__ __forceinline__ void mma_tf32(float* c, const u32* a, const u32* b){
    asm volatile(
        "mma.sync.aligned.m16n8k8.row.col.f32.tf32.tf32.f32 "
        "{%0,%1,%2,%3}, {%4,%5,%6,%7}, {%8,%9}, {%0,%1,%2,%3};"
        : "+f"(c[0]), "+f"(c[1]), "+f"(c[2]), "+f"(c[3])
        : "r"(a[0]), "r"(a[1]), "r"(a[2]), "r"(a[3]), "r"(b[0]), "r"(b[1]));
}

// =====================================================================
// K1: QKV projections via tf32 mma. grid (16, 12, 3). 256 thr.
// =====================================================================
__global__ __launch_bounds__(256) void k_proj(
    const float* __restrict__ Xq, const float* __restrict__ Xk, const float* __restrict__ Xv,
    const float* __restrict__ Wq, const float* __restrict__ Wk, const float* __restrict__ Wv,
    const float* __restrict__ bq, const float* __restrict__ bk, const float* __restrict__ bv)
{
    const int z = blockIdx.z;
    const float* X    = (z == 0) ? Xq : (z == 1) ? Xk : Xv;
    const float* W    = (z == 0) ? Wq : (z == 1) ? Wk : Wv;
    const float* bias = (z == 0) ? bq : (z == 1) ? bk : bv;
    float* out        = (z == 0) ? g_q : (z == 1) ? g_k : g_v;
    const float scale = (z == 0) ? (1.0f / 64.0f) : 1.0f;

    __shared__ __align__(16) u32 As[128][36];
    __shared__ __align__(16) u32 Bs[32][72];

    const int tid = threadIdx.x;
    const int lane = tid & 31;
    const int warp = tid >> 5;
    const int wm = warp >> 1;
    const int wn = warp & 1;
    const int rq = lane >> 2;
    const int cq = lane & 3;
    const int m0 = blockIdx.x * 128;
    const int h  = blockIdx.y;
    const int n0 = h * 64;

    float acc[2][4][4];
    #pragma unroll
    for (int i = 0; i < 2; i++)
        #pragma unroll
        for (int j = 0; j < 4; j++)
            #pragma unroll
            for (int t = 0; t < 4; t++) acc[i][j][t] = 0.f;

    float4 pfa[4], pfb[2];
    #pragma unroll
    for (int it = 0; it < 4; it++) {
        int f = tid + it * 256;
        pfa[it] = *(const float4*)(X + (size_t)(m0 + (f >> 3)) * DM + (f & 7) * 4);
    }
    #pragma unroll
    for (int it = 0; it < 2; it++) {
        int f = tid + it * 256;
        pfb[it] = *(const float4*)(W + (size_t)(f >> 4) * DM + n0 + (f & 15) * 4);
    }

    for (int k0 = 0; k0 < DM; k0 += 32) {
        __syncthreads();
        #pragma unroll
        for (int it = 0; it < 4; it++) {
            int f = tid + it * 256;
            *(uint4*)&As[f >> 3][(f & 7) * 4] = cvt4(pfa[it]);
        }
        #pragma unroll
        for (int it = 0; it < 2; it++) {
            int f = tid + it * 256;
            *(uint4*)&Bs[f >> 4][(f & 15) * 4] = cvt4(pfb[it]);
        }
        __syncthreads();

        if (k0 + 32 < DM) {
            #pragma unroll
            for (int it = 0; it < 4; it++) {
                int f = tid + it * 256;
                pfa[it] = *(const float4*)(X + (size_t)(m0 + (f >> 3)) * DM + k0 + 32 + (f & 7) * 4);
            }
            #pragma unroll
            for (int it = 0; it < 2; it++) {
                int f = tid + it * 256;
                pfb[it] = *(const float4*)(W + (size_t)(k0 + 32 + (f >> 4)) * DM + n0 + (f & 15) * 4);
            }
        }

        #pragma unroll
        for (int ks = 0; ks < 4; ks++) {
            int kk = ks * 8;
            u32 a[2][4], bf[4][2];
            #pragma unroll
            for (int mi = 0; mi < 2; mi++) {
                int r = wm * 32 + mi * 16 + rq;
                a[mi][0] = As[r][kk + cq];
                a[mi][1] = As[r + 8][kk + cq];
                a[mi][2] = As[r][kk + cq + 4];
                a[mi][3] = As[r + 8][kk + cq + 4];
            }
            #pragma unroll
            for (int ni = 0; ni < 4; ni++) {
                int n = wn * 32 + ni * 8 + rq;
                bf[ni][0] = Bs[kk + cq][n];
                bf[ni][1] = Bs[kk + cq + 4][n];
            }
            #pragma unroll
            for (int mi = 0; mi < 2; mi++)
                #pragma unroll
                for (int ni = 0; ni < 4; ni++)
                    mma_tf32(acc[mi][ni], a[mi], bf[ni]);
        }
    }

    #pragma unroll
    for (int mi = 0; mi < 2; mi++) {
        #pragma unroll
        for (int ni = 0; ni < 4; ni++) {
            int ncol = wn * 32 + ni * 8 + cq * 2;
            float bx = bias[n0 + ncol];
            float by = bias[n0 + ncol + 1];
            int m = m0 + wm * 32 + mi * 16 + rq;
            {
                int b = m >> 10, s = m & (SQ - 1);
                float* dst = out + ((size_t)((b * NH + h) * SQ + s)) * DK + ncol;
                *(float2*)dst = make_float2((acc[mi][ni][0] + bx) * scale,
                                            (acc[mi][ni][1] + by) * scale);
            }
            {
                int m2 = m + 8;
                int b = m2 >> 10, s = m2 & (SQ - 1);
                float* dst = out + ((size_t)((b * NH + h) * SQ + s)) * DK + ncol;
                *(float2*)dst = make_float2((acc[mi][ni][2] + bx) * scale,
                                            (acc[mi][ni][3] + by) * scale);
            }
        }
    }
}

// =====================================================================
// K2: scores = q @ k^T for batch b. grid (8, 8, 12), dyn smem 69632 B.
// =====================================================================
__global__ __launch_bounds__(256) void k_qk(int batch)
{
    extern __shared__ __align__(16) u32 smu[];
    u32 (*Qs)[68] = (u32(*)[68])smu;
    u32 (*Ks)[68] = (u32(*)[68])(smu + 128 * 68);

    const int bh = batch * NH + blockIdx.z;
    const float* Aq = g_q + (size_t)bh * SQ * DK;
    const float* Bk = g_k + (size_t)bh * SQ * DK;
    float* C = g_scores + (size_t)bh * SQ * SQ;

    const int m0 = blockIdx.x * 128;
    const int n0 = blockIdx.y * 128;
    const int tid = threadIdx.x;
    const int lane = tid & 31;
    const int warp = tid >> 5;
    const int wm = warp >> 2;
    const int wn = warp & 3;
    const int rq = lane >> 2;
    const int cq = lane & 3;

    #pragma unroll
    for (int it = 0; it < 8; it++) {
        int f = tid + it * 256;
        int r  = f >> 4;
        int d4 = (f & 15) * 4;
        float4 va = *(const float4*)(Aq + (size_t)(m0 + r) * DK + d4);
        float4 vb = *(const float4*)(Bk + (size_t)(n0 + r) * DK + d4);
        *(uint4*)&Qs[r][d4] = cvt4(va);
        *(uint4*)&Ks[r][d4] = cvt4(vb);
    }
    __syncthreads();

    float acc[4][4][4];
    #pragma unroll
    for (int i = 0; i < 4; i++)
        #pragma unroll
        for (int j = 0; j < 4; j++)
            #pragma unroll
            for (int t = 0; t < 4; t++) acc[i][j][t] = 0.f;

    #pragma unroll
    for (int ks = 0; ks < 8; ks++) {
        int d0 = ks * 8;
        u32 a[4][4], bf[4][2];
        #pragma unroll
        for (int mi = 0; mi < 4; mi++) {
            int r = wm * 64 + mi * 16 + rq;
            a[mi][0] = Qs[r][d0 + cq];
            a[mi][1] = Qs[r + 8][d0 + cq];
            a[mi][2] = Qs[r][d0 + cq + 4];
            a[mi][3] = Qs[r + 8][d0 + cq + 4];
        }
        #pragma unroll
        for (int ni = 0; ni < 4; ni++) {
            int n = wn * 32 + ni * 8 + rq;
            bf[ni][0] = Ks[n][d0 + cq];
            bf[ni][1] = Ks[n][d0 + cq + 4];
        }
        #pragma unroll
        for (int mi = 0; mi < 4; mi++)
            #pragma unroll
            for (int ni = 0; ni < 4; ni++)
                mma_tf32(acc[mi][ni], a[mi], bf[ni]);
    }

    #pragma unroll
    for (int mi = 0; mi < 4; mi++) {
        #pragma unroll
        for (int ni = 0; ni < 4; ni++) {
            int r0 = m0 + wm * 64 + mi * 16 + rq;
            int c0 = n0 + wn * 32 + ni * 8 + cq * 2;
            *(float2*)(C + (size_t)r0 * SQ + c0)       = make_float2(acc[mi][ni][0], acc[mi][ni][1]);
            *(float2*)(C + (size_t)(r0 + 8) * SQ + c0) = make_float2(acc[mi][ni][2], acc[mi][ni][3]);
        }
    }
}

// =====================================================================
// K3: qrel + softmax for batch b. 512 threads. grid (1024), smem 88064 B.
// =====================================================================
__global__ __launch_bounds__(512) void k_qrel_sm(const float* __restrict__ relk, int batch)
{
    extern __shared__ __align__(16) float sm[];
    float* ss = sm;                                        // 12*1024 floats
    u32 (*rks)[68] = (u32(*)[68])(sm + NH * SQ);           // 128*68 tf32
    u32 (*qs)[64] = (u32(*)[64])(sm + NH * SQ + 128 * 68); // 16*64 tf32 (rows 12-15 zero)

    const int b = batch, q = blockIdx.x;
    const int tid = threadIdx.x;
    const int lane = tid & 31;
    const int warp = tid >> 5;       // 0..15
    const int rq = lane >> 2;        // 0..7
    const int cq = lane & 3;         // 0..3
    const int n0c = warp * 8;

    if (tid < 192) {
        int hh = tid >> 4;
        int d4 = (tid & 15) * 4;
        float4 v = *(const float4*)(g_q + ((size_t)((b * NH + hh) * SQ + q)) * DK + d4);
        *(uint4*)&qs[hh][d4] = cvt4(v);
    } else if (tid < 256) {
        int r = 12 + ((tid - 192) >> 4);
        int d4 = ((tid - 192) & 15) * 4;
        *(uint4*)&qs[r][d4] = make_uint4(0u, 0u, 0u, 0u);
    }
    #pragma unroll
    for (int it = 0; it < 6; it++) {
        int f = tid + it * 512;
        int hh = f >> 8;
        int k4 = (f & 255) * 4;
        *(float4*)&ss[hh * SQ + k4] =
            *(const float4*)(g_scores + ((size_t)((b * NH + hh) * SQ + q)) * SQ + k4);
    }

    const float* relbase = relk + ((size_t)(b * SQ + q)) * SQ * DK;

    float4 pf[4];
    #pragma unroll
    for (int it = 0; it < 4; it++) {
        int f = tid + it * 512;
        pf[it] = *(const float4*)(relbase + (size_t)(f >> 4) * DK + (f & 15) * 4);
    }
    __syncthreads();

    u32 afrag[8][4];
    #pragma unroll
    for (int ks = 0; ks < 8; ks++) {
        int d0 = ks * 8;
        afrag[ks][0] = qs[rq][d0 + cq];
        afrag[ks][1] = qs[rq + 8][d0 + cq];
        afrag[ks][2] = qs[rq][d0 + cq + 4];
        afrag[ks][3] = qs[rq + 8][d0 + cq + 4];
    }

    for (int kt = 0; kt < SQ; kt += 128) {
        __syncthreads();
        #pragma unroll
        for (int it = 0; it < 4; it++) {
            int f = tid + it * 512;
            *(uint4*)&rks[f >> 4][(f & 15) * 4] = cvt4(pf[it]);
        }
        __syncthreads();

        if (kt + 128 < SQ) {
            #pragma unroll
            for (int it = 0; it < 4; it++) {
                int f = tid + it * 512;
                pf[it] = *(const float4*)(relbase + (size_t)(kt + 128 + (f >> 4)) * DK + (f & 15) * 4);
            }
        }

        float acc[4] = {0.f, 0.f, 0.f, 0.f};
        #pragma unroll
        for (int ks = 0; ks < 8; ks++) {
            int d0 = ks * 8;
            u32 bf[2];
            bf[0] = rks[n0c + rq][d0 + cq];
            bf[1] = rks[n0c + rq][d0 + cq + 4];
            mma_tf32(acc, afrag[ks], bf);
        }

        int col = kt + n0c + cq * 2;
        ss[rq * SQ + col]     += acc[0];
        ss[rq * SQ + col + 1] += acc[1];
        if (rq < 4) {
            ss[(rq + 8) * SQ + col]     += acc[2];
            ss[(rq + 8) * SQ + col + 1] += acc[3];
        }
    }
    __syncthreads();

    const int swarp = tid >> 5;
    const int slane = tid & 31;
    if (swarp < NH) {
        float* p = ss + swarp * SQ;
        float4 v[8];
        float mx = -3.4e38f;
        #pragma unroll
        for (int j = 0; j < 8; j++) {
            v[j] = *(float4*)(p + slane * 4 + j * 128);
            mx = fmaxf(mx, fmaxf(fmaxf(v[j].x, v[j].y), fmaxf(v[j].z, v[j].w)));
        }
        #pragma unroll
        for (int o = 16; o > 0; o >>= 1) mx = fmaxf(mx, __shfl_xor_sync(0xffffffffu, mx, o));

        float s = 0.f;
        #pragma unroll
        for (int j = 0; j < 8; j++) {
            v[j].x = __expf(v[j].x - mx);
            v[j].y = __expf(v[j].y - mx);
            v[j].z = __expf(v[j].z - mx);
            v[j].w = __expf(v[j].w - mx);
            s += v[j].x + v[j].y + v[j].z + v[j].w;
        }
        #pragma unroll
        for (int o = 16; o > 0; o >>= 1) s += __shfl_xor_sync(0xffffffffu, s, o);
        const float inv = 1.0f / s;

        float* dst = g_scores + ((size_t)((b * NH + swarp) * SQ + q)) * SQ;
        #pragma unroll
        for (int j = 0; j < 8; j++) {
            v[j].x *= inv; v[j].y *= inv; v[j].z *= inv; v[j].w *= inv;
            *(float4*)(dst + slane * 4 + j * 128) = v[j];
        }
    }
}

// =====================================================================
// K5+K6 (k_pv) for one batch: grid 1216 CTAs.
//   [0, 1024): w_rel -> g_attn ; [1024, 1216): wv -> g_attn2/g_attn3
// 256 threads, dyn smem 45312 B.
// =====================================================================
__global__ __launch_bounds__(256) void k_pv(const float* __restrict__ relv, int batch)
{
    extern __shared__ __align__(16) u32 dyn[];

    const int tid = threadIdx.x;
    const int lane = tid & 31;
    const int warp = tid >> 5;
    const int rq = lane >> 2;
    const int cq = lane & 3;
    const int b = batch;

    if (blockIdx.x < 1024) {
        // ---------------- w_rel path ----------------
        u32 (*rvs)[72] = (u32(*)[72])dyn;                 // 128x72
        u32 (*ps)[132] = (u32(*)[132])(dyn + 128 * 72);   // 16x132

        const int q = blockIdx.x;
        const int n0c = warp * 8;

        {
            int r = 12 + (tid >> 6);
            int c = (tid & 63) * 2;
            ps[r][c] = 0u; ps[r][c + 1] = 0u;
        }

        const float* relbase = relv + ((size_t)(b * SQ + q)) * SQ * DK;
        const float* psrc = g_scores + ((size_t)(b * NH) * SQ + q) * SQ;

        float acc[4] = {0.f, 0.f, 0.f, 0.f};

        float4 pfr[8], pfp[2];
        #pragma unroll
        for (int it = 0; it < 8; it++) {
            int f = tid + it * 256;
            pfr[it] = *(const float4*)(relbase + (size_t)(f >> 4) * DK + (f & 15) * 4);
        }
        #pragma unroll
        for (int it = 0; it < 2; it++) {
            int f = tid + it * 256;
            if (f < 384)
                pfp[it] = *(const float4*)(psrc + (size_t)(f >> 5) * SQ * SQ + (f & 31) * 4);
        }

        for (int kt = 0; kt < SQ; kt += 128) {
            __syncthreads();
            #pragma unroll
            for (int it = 0; it < 8; it++) {
                int f = tid + it * 256;
                *(uint4*)&rvs[f >> 4][(f & 15) * 4] = cvt4(pfr[it]);
            }
            #pragma unroll
            for (int it = 0; it < 2; it++) {
                int f = tid + it * 256;
                if (f < 384)
                    *(uint4*)&ps[f >> 5][(f & 31) * 4] = cvt4(pfp[it]);
            }
            __syncthreads();

            if (kt + 128 < SQ) {
                #pragma unroll
                for (int it = 0; it < 8; it++) {
                    int f = tid + it * 256;
                    pfr[it] = *(const float4*)(relbase + (size_t)(kt + 128 + (f >> 4)) * DK + (f & 15) * 4);
                }
                #pragma unroll
                for (int it = 0; it < 2; it++) {
                    int f = tid + it * 256;
                    if (f < 384)
                        pfp[it] = *(const float4*)(psrc + (size_t)(f >> 5) * SQ * SQ + kt + 128 + (f & 31) * 4);
                }
            }

            #pragma unroll
            for (int ks = 0; ks < 16; ks++) {
                int kk = ks * 8;
                u32 a[4], bf[2];
                a[0] = ps[rq][kk + cq];
                a[1] = ps[rq + 8][kk + cq];
                a[2] = ps[rq][kk + cq + 4];
                a[3] = ps[rq + 8][kk + cq + 4];
                bf[0] = rvs[kk + cq][n0c + rq];
                bf[1] = rvs[kk + cq + 4][n0c + rq];
                mma_tf32(acc, a, bf);
            }
        }

        const size_t base = (size_t)(b * SQ + q) * DM;
        const int col = n0c + cq * 2;
        *(float2*)(g_attn + base + rq * DK + col) = make_float2(acc[0], acc[1]);
        if (rq < 4)
            *(float2*)(g_attn + base + (rq + 8) * DK + col) = make_float2(acc[2], acc[3]);
    } else {
        // ---------------- wv path ----------------
        u32 (*As)[36] = (u32(*)[36])dyn;                 // 128x36
        u32 (*Bs)[72] = (u32(*)[72])(dyn + 128 * 36);    // 32x72

        const int idx = blockIdx.x - 1024;   // [0, 192)
        const int m0 = (idx & 7) * 128;
        const int h = (idx >> 3) % NH;
        const int kz = idx / 96;
        const int bh = b * NH + h;
        const int koff = kz * 512;
        const float* A  = g_scores + (size_t)bh * SQ * SQ + koff;
        const float* Bv = g_v + ((size_t)bh * SQ + koff) * DK;
        float* outp = kz ? g_attn3 : g_attn2;

        const int wm = warp >> 1;
        const int wn = warp & 1;

        float acc[2][4][4];
        #pragma unroll
        for (int i = 0; i < 2; i++)
            #pragma unroll
            for (int j = 0; j < 4; j++)
                #pragma unroll
                for (int t = 0; t < 4; t++) acc[i][j][t] = 0.f;

        float4 pfa[4], pfb[2];
        #pragma unroll
        for (int it = 0; it < 4; it++) {
            int f = tid + it * 256;
            pfa[it] = *(const float4*)(A + (size_t)(m0 + (f >> 3)) * SQ + (f & 7) * 4);
        }
        #pragma unroll
        for (int it = 0; it < 2; it++) {
            int f = tid + it * 256;
            pfb[it] = *(const float4*)(Bv + (size_t)(f >> 4) * DK + (f & 15) * 4);
        }

        for (int k0 = 0; k0 < 512; k0 += 32) {
            __syncthreads();
            #pragma unroll
            for (int it = 0; it < 4; it++) {
                int f = tid + it * 256;
                *(uint4*)&As[f >> 3][(f & 7) * 4] = cvt4(pfa[it]);
            }
            #pragma unroll
            for (int it = 0; it < 2; it++) {
                int f = tid + it * 256;
                *(uint4*)&Bs[f >> 4][(f & 15) * 4] = cvt4(pfb[it]);
            }
            __syncthreads();

            if (k0 + 32 < 512) {
                #pragma unroll
                for (int it = 0; it < 4; it++) {
                    int f = tid + it * 256;
                    pfa[it] = *(const float4*)(A + (size_t)(m0 + (f >> 3)) * SQ + k0 + 32 + (f & 7) * 4);
                }
                #pragma unroll
                for (int it = 0; it < 2; it++) {
                    int f = tid + it * 256;
                    pfb[it] = *(const float4*)(Bv + (size_t)(k0 + 32 + (f >> 4)) * DK + (f & 15) * 4);
                }
            }

            #pragma unroll
            for (int ks = 0; ks < 4; ks++) {
                int kk = ks * 8;
                u32 a[2][4], bf[4][2];
                #pragma unroll
                for (int mi = 0; mi < 2; mi++) {
                    int r = wm * 32 + mi * 16 + rq;
                    a[mi][0] = As[r][kk + cq];
                    a[mi][1] = As[r + 8][kk + cq];
                    a[mi][2] = As[r][kk + cq + 4];
                    a[mi][3] = As[r + 8][kk + cq + 4];
                }
                #pragma unroll
                for (int ni = 0; ni < 4; ni++) {
                    int n = wn * 32 + ni * 8 + rq;
                    bf[ni][0] = Bs[kk + cq][n];
                    bf[ni][1] = Bs[kk + cq + 4][n];
                }
                #pragma unroll
                for (int mi = 0; mi < 2; mi++)
                    #pragma unroll
                    for (int ni = 0; ni < 4; ni++)
                        mma_tf32(acc[mi][ni], a[mi], bf[ni]);
            }
        }

        #pragma unroll
        for (int mi = 0; mi < 2; mi++) {
            #pragma unroll
            for (int ni = 0; ni < 4; ni++) {
                int r0 = m0 + wm * 32 + mi * 16 + rq;
                int c0 = wn * 32 + ni * 8 + cq * 2;
                float* dst0 = outp + (size_t)(b * SQ + r0) * DM + h * DK + c0;
                float* dst1 = outp + (size_t)(b * SQ + r0 + 8) * DM + h * DK + c0;
                *(float2*)dst0 = make_float2(acc[mi][ni][0], acc[mi][ni][1]);
                *(float2*)dst1 = make_float2(acc[mi][ni][2], acc[mi][ni][3]);
            }
        }
    }
}

// =====================================================================
// K7: out = (g_attn + g_attn2 + g_attn3) @ Wo + bo for one batch.
// BM=64, BN=64, BK=32. grid (16, 12). dyn smem 18432 B.
// =====================================================================
__global__ __launch_bounds__(256) void k_out(
    const float* __restrict__ Wo, const float* __restrict__ bo,
    float* __restrict__ out, int batch)
{
    extern __shared__ __align__(16) u32 osm[];
    u32 (*As)[36] = (u32(*)[36])osm;
    u32 (*Bs)[72] = (u32(*)[72])(osm + 64 * 36);

    const int tid = threadIdx.x;
    const int lane = tid & 31;
    const int warp = tid >> 5;
    const int wm = warp >> 1;
    const int wn = warp & 1;
    const int rq = lane >> 2;
    const int cq = lane & 3;
    const int m0 = batch * SQ + blockIdx.x * 64;
    const int n0 = blockIdx.y * 64;

    float acc[4][4];
    #pragma unroll
    for (int j = 0; j < 4; j++)
        #pragma unroll
        for (int t = 0; t < 4; t++) acc[j][t] = 0.f;

    float4 pfa[2], pfb[2];
    #pragma unroll
    for (int it = 0; it < 2; it++) {
        int f = tid + it * 256;
        size_t idx = (size_t)(m0 + (f >> 3)) * DM + (f & 7) * 4;
        float4 a1 = *(const float4*)(g_attn + idx);
        float4 a2 = *(const float4*)(g_attn2 + idx);
        float4 a3 = *(const float4*)(g_attn3 + idx);
        pfa[it] = make_float4(a1.x + a2.x + a3.x, a1.y + a2.y + a3.y,
                              a1.z + a2.z + a3.z, a1.w + a2.w + a3.w);
        pfb[it] = *(const float4*)(Wo + (size_t)(f >> 4) * DM + n0 + (f & 15) * 4);
    }

    for (int k0 = 0; k0 < DM; k0 += 32) {
        __syncthreads();
        #pragma unroll
        for (int it = 0; it < 2; it++) {
            int f = tid + it * 256;
            *(uint4*)&As[f >> 3][(f & 7) * 4] = cvt4(pfa[it]);
            *(uint4*)&Bs[f >> 4][(f & 15) * 4] = cvt4(pfb[it]);
        }
        __syncthreads();

        if (k0 + 32 < DM) {
            #pragma unroll
            for (int it = 0; it < 2; it++) {
                int f = tid + it * 256;
                size_t idx = (size_t)(m0 + (f >> 3)) * DM + k0 + 32 + (f & 7) * 4;
                float4 a1 = *(const float4*)(g_attn + idx);
                float4 a2 = *(const float4*)(g_attn2 + idx);
                float4 a3 = *(const float4*)(g_attn3 + idx);
                pfa[it] = make_float4(a1.x + a2.x + a3.x, a1.y + a2.y + a3.y,
                                      a1.z + a2.z + a3.z, a1.w + a2.w + a3.w);
                pfb[it] = *(const float4*)(Wo + (size_t)(k0 + 32 + (f >> 4)) * DM + n0 + (f & 15) * 4);
            }
        }

        #pragma unroll
        for (int ks = 0; ks < 4; ks++) {
            int kk = ks * 8;
            u32 a[4], bf[4][2];
            int r = wm * 16 + rq;
            a[0] = As[r][kk + cq];
            a[1] = As[r + 8][kk + cq];
            a[2] = As[r][kk + cq + 4];
            a[3] = As[r + 8][kk + cq + 4];
            #pragma unroll
            for (int ni = 0; ni < 4; ni++) {
                int n = wn * 32 + ni * 8 + rq;
                bf[ni][0] = Bs[kk + cq][n];
                bf[ni][1] = Bs[kk + cq + 4][n];
            }
            #pragma unroll
            for (int ni = 0; ni < 4; ni++)
                mma_tf32(acc[ni], a, bf[ni]);
        }
    }

    #pragma unroll
    for (int ni = 0; ni < 4; ni++) {
        int ncol = wn * 32 + ni * 8 + cq * 2;
        float bx = bo[n0 + ncol];
        float by = bo[n0 + ncol + 1];
        int m = m0 + wm * 16 + rq;
        *(float2*)(out + (size_t)m * DM + n0 + ncol) =
            make_float2(acc[ni][0] + bx, acc[ni][1] + by);
        *(float2*)(out + (size_t)(m + 8) * DM + n0 + ncol) =
            make_float2(acc[ni][2] + bx, acc[ni][3] + by);
    }
}

// =====================================================================
extern "C" void kernel_launch(void* const* d_in, const int* in_sizes, int n_in,
                              void* d_out, int out_size)
{
    const float* queries = (const float*)d_in[0];
    const float* keys    = (const float*)d_in[1];
    const float* values  = (const float*)d_in[2];
    const float* relk    = (const float*)d_in[3];
    const float* relv    = (const float*)d_in[4];
    const float* Wq = (const float*)d_in[5];
    const float* bq = (const float*)d_in[6];
    const float* Wk = (const float*)d_in[7];
    const float* bk = (const float*)d_in[8];
    const float* Wv = (const float*)d_in[9];
    const float* bv = (const float*)d_in[10];
    const float* Wo = (const float*)d_in[11];
    const float* bo = (const float*)d_in[12];
    float* out = (float*)d_out;

    const int qk_smem   = 2 * 128 * 68 * (int)sizeof(u32);               // 69632
    const int qrel_smem = NH * SQ * (int)sizeof(float)
                        + 128 * 68 * (int)sizeof(u32)
                        + 16 * 64 * (int)sizeof(u32);                    // 88064
    const int pv_smem   = (128 * 72 + 16 * 132) * (int)sizeof(u32);      // 45312
    const int out_smem  = (64 * 36 + 32 * 72) * (int)sizeof(u32);        // 18432

    static cudaStream_t s1 = nullptr;
    static cudaEvent_t eFork = nullptr, eJoin = nullptr;
    static bool init_done = false;
    if (!init_done) {
        cudaFuncSetAttribute(k_qk, cudaFuncAttributeMaxDynamicSharedMemorySize, qk_smem);
        cudaFuncSetAttribute(k_qrel_sm, cudaFuncAttributeMaxDynamicSharedMemorySize, qrel_smem);
        cudaFuncSetAttribute(k_pv, cudaFuncAttributeMaxDynamicSharedMemorySize, pv_smem);
        cudaFuncSetAttribute(k_out, cudaFuncAttributeMaxDynamicSharedMemorySize, out_smem);
        cudaStreamCreateWithFlags(&s1, cudaStreamNonBlocking);
        cudaEventCreateWithFlags(&eFork, cudaEventDisableTiming);
        cudaEventCreateWithFlags(&eJoin, cudaEventDisableTiming);
        init_done = true;
    }

    // stage 0: projections (stream 0)
    k_proj<<<dim3(16, 12, 3), 256>>>(queries, keys, values, Wq, Wk, Wv, bq, bk, bv);

    // fork: stream 1 handles batch 1 chain
    cudaEventRecord(eFork, 0);
    cudaStreamWaitEvent(s1, eFork, 0);

    // batch 0 chain on stream 0
    k_qk<<<dim3(8, 8, NH), 256, qk_smem>>>(0);
    k_qrel_sm<<<dim3(SQ), 512, qrel_smem>>>(relk, 0);
    k_pv<<<dim3(1024 + 192), 256, pv_smem>>>(relv, 0);
    k_out<<<dim3(16, 12), 256, out_smem>>>(Wo, bo, out, 0);

    // batch 1 chain on stream 1
    k_qk<<<dim3(8, 8, NH), 256, qk_smem, s1>>>(1);
    k_qrel_sm<<<dim3(SQ), 512, qrel_smem, s1>>>(relk, 1);
    k_pv<<<dim3(1024 + 192), 256, pv_smem, s1>>>(relv, 1);
    k_out<<<dim3(16, 12), 256, out_smem, s1>>>(Wo, bo, out, 1);

    // join
    cudaEventRecord(eJoin, s1);
    cudaStreamWaitEvent(0, eJoin, 0);
}